// round 6
// baseline (speedup 1.0000x reference)
#include <cuda_runtime.h>
#include <cuda_bf16.h>

// velocity = MLP(concat(zone_embedding, person_attrs, time_vec)).
// GCN layers are dead code w.r.t. the output; person/time layer-1
// contributions are row-constant, folded into g_c1 by setup_kernel.
//
// R6: weights moved to __constant__ memory (LDC = the hardware uniform-
// broadcast port, separate from L1TEX which charges per-lane bytes for
// broadcasts — proven in R3/R4). Populated by cudaMemcpyToSymbolAsync (D2D,
// graph-capturable). Kernel keeps R5's 4-rows/thread register blocking;
// L1TEX now carries only the z tile and stores. Expect pure fma-bound.

#define HID 32
#define H1  64
#define TPB 64
#define RPB 256

typedef unsigned long long u64;

__device__ __align__(16) float g_c1[H1];

// Constant-bank weights (20KB total, <64KB).
__constant__ ulonglong2 cW1v[512];   // Wd1 zone part [k=32][16 ull2/row]
__constant__ ulonglong2 cW2v[512];   // Wd2 [k=64][8 ull2/row]
__constant__ ulonglong2 cW3v[256];   // Wd3 [k=32][8 ull2/row]

__device__ __forceinline__ u64 fma2(u64 a, u64 b, u64 c) {
    u64 d;
    asm("fma.rn.f32x2 %0, %1, %2, %3;" : "=l"(d) : "l"(a), "l"(b), "l"(c));
    return d;
}
__device__ __forceinline__ u64 dup2(float x) {
    u64 d;
    asm("mov.b64 %0, {%1, %1};" : "=l"(d) : "f"(x));
    return d;
}
__device__ __forceinline__ float2 unpk2(u64 v) {
    float2 r;
    asm("mov.b64 {%0, %1}, %2;" : "=f"(r.x), "=f"(r.y) : "l"(v));
    return r;
}

// ---------------------------------------------------------------------------
__global__ void setup_kernel(const float* __restrict__ t,
                             const float* __restrict__ pa,
                             const float* __restrict__ Wt1, const float* __restrict__ bt1,
                             const float* __restrict__ Wt2, const float* __restrict__ bt2,
                             const float* __restrict__ Wd1, const float* __restrict__ bd1)
{
    __shared__ float u[16];
    __shared__ float tv[16];
    const int j = threadIdx.x;

    if (j < 16) u[j] = fmaxf(fmaf(t[0], Wt1[j], bt1[j]), 0.0f);
    __syncthreads();

    if (j < 16) {
        float a = bt2[j];
        #pragma unroll
        for (int i = 0; i < 16; i++) a = fmaf(u[i], Wt2[i * 16 + j], a);
        tv[j] = a;
    }
    __syncthreads();

    if (j < H1) {
        float a = bd1[j];
        #pragma unroll
        for (int p = 0; p < 8; p++)  a = fmaf(pa[p], Wd1[(HID + p) * H1 + j], a);
        #pragma unroll
        for (int i = 0; i < 16; i++) a = fmaf(tv[i], Wd1[(HID + 8 + i) * H1 + j], a);
        g_c1[j] = a;
    }
}

// ---------------------------------------------------------------------------
// 64 threads/block, 256 rows/block, thread t owns rows 4t..4t+3.
// ---------------------------------------------------------------------------
__global__ void __launch_bounds__(TPB)
mlp_kernel(const float* __restrict__ emb,
           const float* __restrict__ bd2, const float* __restrict__ bd3,
           float* __restrict__ out, int nrows)
{
    __shared__ __align__(16) float z_s[32][RPB];   // transposed z tile, 32KB

    const int tid = threadIdx.x;
    const int rb  = blockIdx.x * RPB;

    // --- stage z tile transposed ---
    {
        const float4* ev = reinterpret_cast<const float4*>(emb);
        #pragma unroll
        for (int i = tid; i < RPB * 8; i += TPB) {
            int row = i & (RPB - 1);
            int c4  = i >> 8;
            if (rb + row < nrows) {
                float4 v = ev[(size_t)(rb + row) * 8 + c4];
                z_s[4 * c4 + 0][row] = v.x;
                z_s[4 * c4 + 1][row] = v.y;
                z_s[4 * c4 + 2][row] = v.z;
                z_s[4 * c4 + 3][row] = v.w;
            }
        }
    }
    __syncthreads();

    // --- fused layer1 -> relu -> layer2 accumulate (acc2 in regs) ---
    u64 acc2[4][16];
    #pragma unroll
    for (int r = 0; r < 4; r++)
        #pragma unroll
        for (int q = 0; q < 16; q++) acc2[r][q] = 0ull;   // b2 added later

    for (int c = 0; c < 4; ++c) {                 // 16 h1 outs per chunk
        u64 a1[4][8];
        {
            const ulonglong2* c1v = reinterpret_cast<const ulonglong2*>(g_c1 + 16 * c);
            ulonglong2 p0 = c1v[0], p1 = c1v[1], p2 = c1v[2], p3 = c1v[3];
            #pragma unroll
            for (int r = 0; r < 4; r++) {
                a1[r][0] = p0.x; a1[r][1] = p0.y;
                a1[r][2] = p1.x; a1[r][3] = p1.y;
                a1[r][4] = p2.x; a1[r][5] = p2.y;
                a1[r][6] = p3.x; a1[r][7] = p3.y;
            }
        }

        #pragma unroll 2
        for (int k = 0; k < 32; ++k) {
            float4 zz = *reinterpret_cast<const float4*>(&z_s[k][4 * tid]);
            u64 zr0 = dup2(zz.x), zr1 = dup2(zz.y), zr2 = dup2(zz.z), zr3 = dup2(zz.w);
            ulonglong2 w0 = cW1v[k * 16 + 4 * c + 0];
            ulonglong2 w1 = cW1v[k * 16 + 4 * c + 1];
            ulonglong2 w2 = cW1v[k * 16 + 4 * c + 2];
            ulonglong2 w3 = cW1v[k * 16 + 4 * c + 3];

            #define L1ROW(r, zr) \
                a1[r][0] = fma2(w0.x, zr, a1[r][0]); a1[r][1] = fma2(w0.y, zr, a1[r][1]); \
                a1[r][2] = fma2(w1.x, zr, a1[r][2]); a1[r][3] = fma2(w1.y, zr, a1[r][3]); \
                a1[r][4] = fma2(w2.x, zr, a1[r][4]); a1[r][5] = fma2(w2.y, zr, a1[r][5]); \
                a1[r][6] = fma2(w3.x, zr, a1[r][6]); a1[r][7] = fma2(w3.y, zr, a1[r][7]);
            L1ROW(0, zr0) L1ROW(1, zr1) L1ROW(2, zr2) L1ROW(3, zr3)
            #undef L1ROW
        }

        // relu(h1 pair) -> accumulate into acc2 (h1 indices 16c+2p, 16c+2p+1)
        #pragma unroll
        for (int p = 0; p < 8; ++p) {
            u64 hA[4], hB[4];
            #pragma unroll
            for (int r = 0; r < 4; r++) {
                float2 h = unpk2(a1[r][p]);
                hA[r] = dup2(fmaxf(h.x, 0.0f));
                hB[r] = dup2(fmaxf(h.y, 0.0f));
            }
            const int ka = (16 * c + 2 * p) * 8;
            const int kb = (16 * c + 2 * p + 1) * 8;
            #pragma unroll
            for (int m = 0; m < 8; ++m) {
                ulonglong2 wa = cW2v[ka + m];
                ulonglong2 wb = cW2v[kb + m];
                #pragma unroll
                for (int r = 0; r < 4; r++) {
                    acc2[r][2 * m]     = fma2(wb.x, hB[r], fma2(wa.x, hA[r], acc2[r][2 * m]));
                    acc2[r][2 * m + 1] = fma2(wb.y, hB[r], fma2(wa.y, hA[r], acc2[r][2 * m + 1]));
                }
            }
        }
    }

    // --- h2 = relu(acc2 + b2); layer3; store ---
    const u64* b2u = reinterpret_cast<const u64*>(bd2);
    const ulonglong2* b3v = reinterpret_cast<const ulonglong2*>(bd3);

    for (int c3 = 0; c3 < 2; ++c3) {              // 16 outs per chunk
        u64 a3[4][8];
        {
            ulonglong2 q0 = b3v[c3 * 4 + 0], q1 = b3v[c3 * 4 + 1];
            ulonglong2 q2 = b3v[c3 * 4 + 2], q3 = b3v[c3 * 4 + 3];
            #pragma unroll
            for (int r = 0; r < 4; r++) {
                a3[r][0] = q0.x; a3[r][1] = q0.y;
                a3[r][2] = q1.x; a3[r][3] = q1.y;
                a3[r][4] = q2.x; a3[r][5] = q2.y;
                a3[r][6] = q3.x; a3[r][7] = q3.y;
            }
        }

        #pragma unroll
        for (int q = 0; q < 16; ++q) {            // h2 pair (2q, 2q+1)
            float2 bb = unpk2(b2u[q]);
            u64 hA[4], hB[4];
            #pragma unroll
            for (int r = 0; r < 4; r++) {
                float2 h = unpk2(acc2[r][q]);
                hA[r] = dup2(fmaxf(h.x + bb.x, 0.0f));
                hB[r] = dup2(fmaxf(h.y + bb.y, 0.0f));
            }
            const int ka = (2 * q) * 8 + 4 * c3;
            const int kb = (2 * q + 1) * 8 + 4 * c3;
            #pragma unroll
            for (int m = 0; m < 4; ++m) {
                ulonglong2 wa = cW3v[ka + m];
                ulonglong2 wb = cW3v[kb + m];
                #pragma unroll
                for (int r = 0; r < 4; r++) {
                    a3[r][2 * m]     = fma2(wb.x, hB[r], fma2(wa.x, hA[r], a3[r][2 * m]));
                    a3[r][2 * m + 1] = fma2(wb.y, hB[r], fma2(wa.y, hA[r], a3[r][2 * m + 1]));
                }
            }
        }

        #pragma unroll
        for (int r = 0; r < 4; r++) {
            int row = rb + 4 * tid + r;
            if (row < nrows) {
                ulonglong2* op = reinterpret_cast<ulonglong2*>(out + (size_t)row * HID + 16 * c3);
                ulonglong2 v0; v0.x = a3[r][0]; v0.y = a3[r][1];
                ulonglong2 v1; v1.x = a3[r][2]; v1.y = a3[r][3];
                ulonglong2 v2; v2.x = a3[r][4]; v2.y = a3[r][5];
                ulonglong2 v3; v3.x = a3[r][6]; v3.y = a3[r][7];
                op[0] = v0; op[1] = v1; op[2] = v2; op[3] = v3;
            }
        }
    }
}

extern "C" void kernel_launch(void* const* d_in, const int* in_sizes, int n_in,
                              void* d_out, int out_size)
{
    const float* t   = (const float*)d_in[0];
    const float* emb = (const float*)d_in[1];
    const float* pa  = (const float*)d_in[3];
    const float* Wt1 = (const float*)d_in[9];
    const float* bt1 = (const float*)d_in[10];
    const float* Wt2 = (const float*)d_in[11];
    const float* bt2 = (const float*)d_in[12];
    const float* Wd1 = (const float*)d_in[13];
    const float* bd1 = (const float*)d_in[14];
    const float* Wd2 = (const float*)d_in[15];
    const float* bd2 = (const float*)d_in[16];
    const float* Wd3 = (const float*)d_in[17];
    const float* bd3 = (const float*)d_in[18];
    float* out = (float*)d_out;

    const int nrows = in_sizes[1] / HID;

    // Weights -> constant bank (async D2D copies; graph-capturable).
    // Wd1 zone part = first 32 rows = first 8KB of Wd1 (row-major [56,64]).
    cudaMemcpyToSymbolAsync(cW1v, Wd1, 32 * 64 * sizeof(float), 0, cudaMemcpyDeviceToDevice);
    cudaMemcpyToSymbolAsync(cW2v, Wd2, 64 * 32 * sizeof(float), 0, cudaMemcpyDeviceToDevice);
    cudaMemcpyToSymbolAsync(cW3v, Wd3, 32 * 32 * sizeof(float), 0, cudaMemcpyDeviceToDevice);

    setup_kernel<<<1, 64>>>(t, pa, Wt1, bt1, Wt2, bt2, Wd1, bd1);
    mlp_kernel<<<(nrows + RPB - 1) / RPB, TPB>>>(emb, bd2, bd3, out, nrows);
}

// round 8
// speedup vs baseline: 1.6745x; 1.6745x over previous
#include <cuda_runtime.h>
#include <cuda_bf16.h>

// velocity = MLP(concat(zone_embedding, person_attrs, time_vec)).
// GCN layers are dead code w.r.t. the output; person/time layer-1
// contributions are row-constant, folded into g_c1 by setup_kernel.
//
// R8 = R7 with dynamic shared memory (52.5KB > 48KB static limit).
// R=2 rows/thread, TPB=128 (12 warps/SM vs R5's 5.3), weights in smem
// (R6: LDC 8-cyc floor too slow for bulk; R4: uniform LDG worst path).

#define HID 32
#define H1  64
#define TPB 128
#define RPB 256

#define ZS_FLOATS (32 * RPB)          // 8192 floats = 32KB
#define WS_FLOATS 5248                // 20.5KB
#define SMEM_BYTES ((ZS_FLOATS + WS_FLOATS) * 4)

typedef unsigned long long u64;

__device__ __align__(16) float g_c1[H1];

__device__ __forceinline__ u64 fma2(u64 a, u64 b, u64 c) {
    u64 d;
    asm("fma.rn.f32x2 %0, %1, %2, %3;" : "=l"(d) : "l"(a), "l"(b), "l"(c));
    return d;
}
__device__ __forceinline__ u64 dup2(float x) {
    u64 d;
    asm("mov.b64 %0, {%1, %1};" : "=l"(d) : "f"(x));
    return d;
}
__device__ __forceinline__ float2 unpk2(u64 v) {
    float2 r;
    asm("mov.b64 {%0, %1}, %2;" : "=f"(r.x), "=f"(r.y) : "l"(v));
    return r;
}

// ---------------------------------------------------------------------------
__global__ void setup_kernel(const float* __restrict__ t,
                             const float* __restrict__ pa,
                             const float* __restrict__ Wt1, const float* __restrict__ bt1,
                             const float* __restrict__ Wt2, const float* __restrict__ bt2,
                             const float* __restrict__ Wd1, const float* __restrict__ bd1)
{
    __shared__ float u[16];
    __shared__ float tv[16];
    const int j = threadIdx.x;

    if (j < 16) u[j] = fmaxf(fmaf(t[0], Wt1[j], bt1[j]), 0.0f);
    __syncthreads();

    if (j < 16) {
        float a = bt2[j];
        #pragma unroll
        for (int i = 0; i < 16; i++) a = fmaf(u[i], Wt2[i * 16 + j], a);
        tv[j] = a;
    }
    __syncthreads();

    if (j < H1) {
        float a = bd1[j];
        #pragma unroll
        for (int p = 0; p < 8; p++)  a = fmaf(pa[p], Wd1[(HID + p) * H1 + j], a);
        #pragma unroll
        for (int i = 0; i < 16; i++) a = fmaf(tv[i], Wd1[(HID + 8 + i) * H1 + j], a);
        g_c1[j] = a;
    }
}

// ---------------------------------------------------------------------------
// 128 threads/block, 256 rows/block; thread t owns rows 2t, 2t+1.
// Dynamic smem: z_s[32][RPB] then w_s[5248]
//   w_s: [0..2047] W1(zone), [2048..4095] W2, [4096..5119] W3,
//        [5120..5183] c1, [5184..5215] b2, [5216..5247] b3.
// ---------------------------------------------------------------------------
__global__ void __launch_bounds__(TPB)
mlp_kernel(const float* __restrict__ emb,
           const float* __restrict__ Wd1,
           const float* __restrict__ Wd2, const float* __restrict__ bd2,
           const float* __restrict__ Wd3, const float* __restrict__ bd3,
           float* __restrict__ out, int nrows)
{
    extern __shared__ __align__(16) float smem[];
    float* z_s = smem;                       // [32][RPB]
    float* w_s = smem + ZS_FLOATS;           // [5248]

    const int tid = threadIdx.x;
    const int rb  = blockIdx.x * RPB;

    // --- stage weights ---
    {
        const float4* w1v = reinterpret_cast<const float4*>(Wd1);  // first 512 f4 = zone rows
        const float4* w2v = reinterpret_cast<const float4*>(Wd2);
        const float4* w3v = reinterpret_cast<const float4*>(Wd3);
        float4* ws = reinterpret_cast<float4*>(w_s);
        #pragma unroll
        for (int i = tid; i < 512; i += TPB)  ws[i]        = w1v[i];
        #pragma unroll
        for (int i = tid; i < 512; i += TPB)  ws[512 + i]  = w2v[i];
        #pragma unroll
        for (int i = tid; i < 256; i += TPB)  ws[1024 + i] = w3v[i];
        if (tid < 64)                    w_s[5120 + tid]        = g_c1[tid];
        else if (tid < 96)               w_s[5184 + (tid - 64)] = bd2[tid - 64];
        else if (tid < 128)              w_s[5216 + (tid - 96)] = bd3[tid - 96];
    }
    // --- stage z tile transposed ---
    {
        const float4* ev = reinterpret_cast<const float4*>(emb);
        #pragma unroll
        for (int i = tid; i < RPB * 8; i += TPB) {
            int row = i & (RPB - 1);
            int c4  = i >> 8;
            if (rb + row < nrows) {
                float4 v = ev[(size_t)(rb + row) * 8 + c4];
                z_s[(4 * c4 + 0) * RPB + row] = v.x;
                z_s[(4 * c4 + 1) * RPB + row] = v.y;
                z_s[(4 * c4 + 2) * RPB + row] = v.z;
                z_s[(4 * c4 + 3) * RPB + row] = v.w;
            }
        }
    }
    __syncthreads();

    // --- fused layer1 -> relu -> layer2 accumulate (acc2 in regs) ---
    u64 acc2[2][16];
    #pragma unroll
    for (int r = 0; r < 2; r++)
        #pragma unroll
        for (int q = 0; q < 16; q++) acc2[r][q] = 0ull;   // b2 added later

    for (int c = 0; c < 4; ++c) {                 // 16 h1 outs per chunk
        u64 a1[2][8];
        {
            const ulonglong2* c1v = reinterpret_cast<const ulonglong2*>(w_s + 5120 + 16 * c);
            ulonglong2 p0 = c1v[0], p1 = c1v[1], p2 = c1v[2], p3 = c1v[3];
            #pragma unroll
            for (int r = 0; r < 2; r++) {
                a1[r][0] = p0.x; a1[r][1] = p0.y;
                a1[r][2] = p1.x; a1[r][3] = p1.y;
                a1[r][4] = p2.x; a1[r][5] = p2.y;
                a1[r][6] = p3.x; a1[r][7] = p3.y;
            }
        }

        const float* wp = w_s + 16 * c;
        #pragma unroll 4
        for (int k = 0; k < 32; ++k) {
            float2 zz = *reinterpret_cast<const float2*>(&z_s[k * RPB + 2 * tid]);
            u64 zr0 = dup2(zz.x), zr1 = dup2(zz.y);
            const ulonglong2* wv = reinterpret_cast<const ulonglong2*>(wp + k * 64);
            ulonglong2 w0 = wv[0], w1 = wv[1], w2 = wv[2], w3 = wv[3];

            #define L1ROW(r, zr) \
                a1[r][0] = fma2(w0.x, zr, a1[r][0]); a1[r][1] = fma2(w0.y, zr, a1[r][1]); \
                a1[r][2] = fma2(w1.x, zr, a1[r][2]); a1[r][3] = fma2(w1.y, zr, a1[r][3]); \
                a1[r][4] = fma2(w2.x, zr, a1[r][4]); a1[r][5] = fma2(w2.y, zr, a1[r][5]); \
                a1[r][6] = fma2(w3.x, zr, a1[r][6]); a1[r][7] = fma2(w3.y, zr, a1[r][7]);
            L1ROW(0, zr0) L1ROW(1, zr1)
            #undef L1ROW
        }

        // relu(h1 pair) -> accumulate into acc2 (h1 indices 16c+2p, 16c+2p+1)
        #pragma unroll
        for (int p = 0; p < 8; ++p) {
            u64 hA[2], hB[2];
            #pragma unroll
            for (int r = 0; r < 2; r++) {
                float2 h = unpk2(a1[r][p]);
                hA[r] = dup2(fmaxf(h.x, 0.0f));
                hB[r] = dup2(fmaxf(h.y, 0.0f));
            }
            const ulonglong2* wra = reinterpret_cast<const ulonglong2*>(w_s + 2048 + (16 * c + 2 * p) * 32);
            const ulonglong2* wrb = reinterpret_cast<const ulonglong2*>(w_s + 2048 + (16 * c + 2 * p + 1) * 32);
            #pragma unroll
            for (int m = 0; m < 8; ++m) {
                ulonglong2 wa = wra[m], wb = wrb[m];
                #pragma unroll
                for (int r = 0; r < 2; r++) {
                    acc2[r][2 * m]     = fma2(wb.x, hB[r], fma2(wa.x, hA[r], acc2[r][2 * m]));
                    acc2[r][2 * m + 1] = fma2(wb.y, hB[r], fma2(wa.y, hA[r], acc2[r][2 * m + 1]));
                }
            }
        }
    }

    // --- h2 = relu(acc2 + b2); layer3 from smem; store ---
    const u64* b2u = reinterpret_cast<const u64*>(w_s + 5184);
    const ulonglong2* b3v = reinterpret_cast<const ulonglong2*>(w_s + 5216);

    for (int c3 = 0; c3 < 2; ++c3) {              // 16 outs per chunk
        u64 a3[2][8];
        {
            ulonglong2 q0 = b3v[c3 * 4 + 0], q1 = b3v[c3 * 4 + 1];
            ulonglong2 q2 = b3v[c3 * 4 + 2], q3 = b3v[c3 * 4 + 3];
            #pragma unroll
            for (int r = 0; r < 2; r++) {
                a3[r][0] = q0.x; a3[r][1] = q0.y;
                a3[r][2] = q1.x; a3[r][3] = q1.y;
                a3[r][4] = q2.x; a3[r][5] = q2.y;
                a3[r][6] = q3.x; a3[r][7] = q3.y;
            }
        }

        #pragma unroll
        for (int q = 0; q < 16; ++q) {            // h2 pair (2q, 2q+1)
            float2 bb = unpk2(b2u[q]);
            u64 hA[2], hB[2];
            #pragma unroll
            for (int r = 0; r < 2; r++) {
                float2 h = unpk2(acc2[r][q]);
                hA[r] = dup2(fmaxf(h.x + bb.x, 0.0f));
                hB[r] = dup2(fmaxf(h.y + bb.y, 0.0f));
            }
            const ulonglong2* wra = reinterpret_cast<const ulonglong2*>(w_s + 4096 + (2 * q) * 32 + 16 * c3);
            const ulonglong2* wrb = reinterpret_cast<const ulonglong2*>(w_s + 4096 + (2 * q + 1) * 32 + 16 * c3);
            #pragma unroll
            for (int m = 0; m < 4; ++m) {
                ulonglong2 wa = wra[m], wb = wrb[m];
                #pragma unroll
                for (int r = 0; r < 2; r++) {
                    a3[r][2 * m]     = fma2(wb.x, hB[r], fma2(wa.x, hA[r], a3[r][2 * m]));
                    a3[r][2 * m + 1] = fma2(wb.y, hB[r], fma2(wa.y, hA[r], a3[r][2 * m + 1]));
                }
            }
        }

        #pragma unroll
        for (int r = 0; r < 2; r++) {
            int row = rb + 2 * tid + r;
            if (row < nrows) {
                ulonglong2* op = reinterpret_cast<ulonglong2*>(out + (size_t)row * HID + 16 * c3);
                ulonglong2 v0; v0.x = a3[r][0]; v0.y = a3[r][1];
                ulonglong2 v1; v1.x = a3[r][2]; v1.y = a3[r][3];
                ulonglong2 v2; v2.x = a3[r][4]; v2.y = a3[r][5];
                ulonglong2 v3; v3.x = a3[r][6]; v3.y = a3[r][7];
                op[0] = v0; op[1] = v1; op[2] = v2; op[3] = v3;
            }
        }
    }
}

extern "C" void kernel_launch(void* const* d_in, const int* in_sizes, int n_in,
                              void* d_out, int out_size)
{
    const float* t   = (const float*)d_in[0];
    const float* emb = (const float*)d_in[1];
    const float* pa  = (const float*)d_in[3];
    const float* Wt1 = (const float*)d_in[9];
    const float* bt1 = (const float*)d_in[10];
    const float* Wt2 = (const float*)d_in[11];
    const float* bt2 = (const float*)d_in[12];
    const float* Wd1 = (const float*)d_in[13];
    const float* bd1 = (const float*)d_in[14];
    const float* Wd2 = (const float*)d_in[15];
    const float* bd2 = (const float*)d_in[16];
    const float* Wd3 = (const float*)d_in[17];
    const float* bd3 = (const float*)d_in[18];
    float* out = (float*)d_out;

    const int nrows = in_sizes[1] / HID;

    static bool attr_set = false;
    if (!attr_set) {
        cudaFuncSetAttribute(mlp_kernel, cudaFuncAttributeMaxDynamicSharedMemorySize, SMEM_BYTES);
        attr_set = true;
    }

    setup_kernel<<<1, 64>>>(t, pa, Wt1, bt1, Wt2, bt2, Wd1, bd1);
    mlp_kernel<<<(nrows + RPB - 1) / RPB, TPB, SMEM_BYTES>>>(emb, Wd1, Wd2, bd2, Wd3, bd3, out, nrows);
}

// round 9
// speedup vs baseline: 3.1468x; 1.8793x over previous
#include <cuda_runtime.h>
#include <cuda_bf16.h>
#include <cstdint>

// velocity = MLP(concat(zone_embedding, person_attrs, time_vec)).
// GCN layers are dead code w.r.t. the output; person/time layer-1
// contributions are row-constant, folded into g_c1 by the prep kernel.
//
// R9: tensor-core path. mma.sync.m16n8k16 bf16 with 3-term split
// (Ahi*Bhi + Ahi*Blo + Alo*Bhi) for ~1e-4 accuracy. The m16n8k16 C-fragment
// layout maps register-for-register onto the next layer's A-fragment, so all
// three layers chain in registers: no smem, no barriers, no shuffles.
// Weights pre-packed into per-lane B-frag uint4 (b0hi,b1hi,b0lo,b1lo) by the
// prep kernel -> each B-frag fetch is one coalesced LDG.128.

#define HID 32
#define H1  64
#define TPB 128            // 4 warps, 32 rows/warp, 128 rows/block

typedef uint32_t u32;

__device__ __align__(16) float g_c1[H1];     // folded layer-1 bias
__device__ uint4 g_W1f[16 * 32];             // (nt8*2 + kt2) x lane
__device__ uint4 g_W2f[16 * 32];             // (nt4*4 + kt4) x lane
__device__ uint4 g_W3f[ 8 * 32];             // (nt4*2 + kt2) x lane

// pack pair (x0 -> low half, x1 -> high half) into bf16x2 hi, residual lo.
__device__ __forceinline__ void split2(float x0, float x1, u32& hi, u32& lo) {
    asm("cvt.rn.bf16x2.f32 %0, %1, %2;" : "=r"(hi) : "f"(x1), "f"(x0));
    float h0 = __uint_as_float(hi << 16);
    float h1 = __uint_as_float(hi & 0xffff0000u);
    float r0 = x0 - h0;
    float r1 = x1 - h1;
    asm("cvt.rn.bf16x2.f32 %0, %1, %2;" : "=r"(lo) : "f"(r1), "f"(r0));
}

__device__ __forceinline__ void mma_bf16(float d[4], const u32 a[4], u32 b0, u32 b1) {
    asm("mma.sync.aligned.m16n8k16.row.col.f32.bf16.bf16.f32 "
        "{%0,%1,%2,%3}, {%4,%5,%6,%7}, {%8,%9}, {%0,%1,%2,%3};"
        : "+f"(d[0]), "+f"(d[1]), "+f"(d[2]), "+f"(d[3])
        : "r"(a[0]), "r"(a[1]), "r"(a[2]), "r"(a[3]), "r"(b0), "r"(b1));
}

// ---------------------------------------------------------------------------
// Prep: fold c1, pack all weight B-fragments (hi/lo). One block, 256 threads.
// B-frag layout (m16n8k16, lane: g=lane>>2, t=lane&3):
//   b0 = { B[16kt+2t][8nt+g] (lo), B[16kt+2t+1][..] (hi) }
//   b1 = { B[16kt+2t+8][..], B[16kt+2t+9][..] }
// ---------------------------------------------------------------------------
__global__ void prep_kernel(const float* __restrict__ t,
                            const float* __restrict__ pa,
                            const float* __restrict__ Wt1, const float* __restrict__ bt1,
                            const float* __restrict__ Wt2, const float* __restrict__ bt2,
                            const float* __restrict__ Wd1, const float* __restrict__ bd1,
                            const float* __restrict__ Wd2, const float* __restrict__ Wd3)
{
    __shared__ float u[16];
    __shared__ float tv[16];
    const int tid = threadIdx.x;

    // --- fold time/person into c1 ---
    if (tid < 16) u[tid] = fmaxf(fmaf(t[0], Wt1[tid], bt1[tid]), 0.0f);
    __syncthreads();
    if (tid < 16) {
        float a = bt2[tid];
        #pragma unroll
        for (int i = 0; i < 16; i++) a = fmaf(u[i], Wt2[i * 16 + tid], a);
        tv[tid] = a;
    }
    __syncthreads();
    if (tid < H1) {
        float a = bd1[tid];
        #pragma unroll
        for (int p = 0; p < 8; p++)  a = fmaf(pa[p], Wd1[(HID + p) * H1 + tid], a);
        #pragma unroll
        for (int i = 0; i < 16; i++) a = fmaf(tv[i], Wd1[(HID + 8 + i) * H1 + tid], a);
        g_c1[tid] = a;
    }

    // --- pack B fragments ---
    for (int idx = tid; idx < 1280; idx += 256) {
        const float* W;
        int stride, nt, kt, lane;
        uint4* dst;
        int slot;
        if (idx < 512) {                 // W1: zone part of Wd1 [32 x 64]
            int s = idx;       lane = s & 31; int ntkt = s >> 5;
            nt = ntkt >> 1; kt = ntkt & 1;
            W = Wd1; stride = 64; dst = g_W1f; slot = s;
        } else if (idx < 1024) {         // W2 [64 x 32]
            int s = idx - 512; lane = s & 31; int ntkt = s >> 5;
            nt = ntkt >> 2; kt = ntkt & 3;
            W = Wd2; stride = 32; dst = g_W2f; slot = s;
        } else {                         // W3 [32 x 32]
            int s = idx - 1024; lane = s & 31; int ntkt = s >> 5;
            nt = ntkt >> 1; kt = ntkt & 1;
            W = Wd3; stride = 32; dst = g_W3f; slot = s;
        }
        int g = lane >> 2, tt = lane & 3;
        int col  = 8 * nt + g;
        int krow = 16 * kt + 2 * tt;
        float w00 = W[(krow    ) * stride + col];
        float w01 = W[(krow + 1) * stride + col];
        float w10 = W[(krow + 8) * stride + col];
        float w11 = W[(krow + 9) * stride + col];
        uint4 f;
        split2(w00, w01, f.x, f.z);     // b0 hi, lo
        split2(w10, w11, f.y, f.w);     // b1 hi, lo
        dst[slot] = f;
    }
}

// ---------------------------------------------------------------------------
// Main: 4 warps/block, 32 rows/warp (2 m16 tiles). All intermediate layers
// live in registers; weights/biases via small coalesced LDG.
// ---------------------------------------------------------------------------
__global__ void __launch_bounds__(TPB)
velo_kernel(const float* __restrict__ emb,
            const float* __restrict__ bd2, const float* __restrict__ bd3,
            float* __restrict__ out, int nrows)
{
    const int warp = threadIdx.x >> 5;
    const int lane = threadIdx.x & 31;
    const int g = lane >> 2, t = lane & 3;
    const int row_base = blockIdx.x * 128 + warp * 32;
    if (row_base >= nrows) return;

    const float2 zero2 = make_float2(0.0f, 0.0f);

    #pragma unroll
    for (int mt = 0; mt < 2; ++mt) {
        const int ra = row_base + 16 * mt + g;
        const int rb = ra + 8;

        // ---- A1 fragments from z (direct LDG, guarded) ----
        u32 A1h[2][4], A1l[2][4];
        #pragma unroll
        for (int kt = 0; kt < 2; ++kt) {
            float2 p0 = (ra < nrows) ? *reinterpret_cast<const float2*>(emb + (size_t)ra * 32 + 16 * kt + 2 * t)     : zero2;
            float2 p1 = (rb < nrows) ? *reinterpret_cast<const float2*>(emb + (size_t)rb * 32 + 16 * kt + 2 * t)     : zero2;
            float2 p2 = (ra < nrows) ? *reinterpret_cast<const float2*>(emb + (size_t)ra * 32 + 16 * kt + 8 + 2 * t) : zero2;
            float2 p3 = (rb < nrows) ? *reinterpret_cast<const float2*>(emb + (size_t)rb * 32 + 16 * kt + 8 + 2 * t) : zero2;
            split2(p0.x, p0.y, A1h[kt][0], A1l[kt][0]);
            split2(p1.x, p1.y, A1h[kt][1], A1l[kt][1]);
            split2(p2.x, p2.y, A1h[kt][2], A1l[kt][2]);
            split2(p3.x, p3.y, A1h[kt][3], A1l[kt][3]);
        }

        // ---- layer1 (K=32, N=64) -> relu -> A2 fragments ----
        u32 A2h[4][4], A2l[4][4];
        #pragma unroll
        for (int nt = 0; nt < 8; ++nt) {
            float d[4] = {0.f, 0.f, 0.f, 0.f};
            #pragma unroll
            for (int kt = 0; kt < 2; ++kt) {
                uint4 B = g_W1f[(nt * 2 + kt) * 32 + lane];
                mma_bf16(d, A1h[kt], B.x, B.y);
                mma_bf16(d, A1h[kt], B.z, B.w);
                mma_bf16(d, A1l[kt], B.x, B.y);
            }
            float2 cb = *reinterpret_cast<const float2*>(g_c1 + 8 * nt + 2 * t);
            float h0 = fmaxf(d[0] + cb.x, 0.0f);
            float h1 = fmaxf(d[1] + cb.y, 0.0f);
            float h2 = fmaxf(d[2] + cb.x, 0.0f);
            float h3 = fmaxf(d[3] + cb.y, 0.0f);
            int kt2 = nt >> 1, off = (nt & 1) * 2;
            split2(h0, h1, A2h[kt2][off],     A2l[kt2][off]);
            split2(h2, h3, A2h[kt2][off + 1], A2l[kt2][off + 1]);
        }

        // ---- layer2 (K=64, N=32) -> relu -> A3 fragments ----
        u32 A3h[2][4], A3l[2][4];
        #pragma unroll
        for (int nt = 0; nt < 4; ++nt) {
            float d[4] = {0.f, 0.f, 0.f, 0.f};
            #pragma unroll
            for (int kt = 0; kt < 4; ++kt) {
                uint4 B = g_W2f[(nt * 4 + kt) * 32 + lane];
                mma_bf16(d, A2h[kt], B.x, B.y);
                mma_bf16(d, A2h[kt], B.z, B.w);
                mma_bf16(d, A2l[kt], B.x, B.y);
            }
            float2 bb = *reinterpret_cast<const float2*>(bd2 + 8 * nt + 2 * t);
            float h0 = fmaxf(d[0] + bb.x, 0.0f);
            float h1 = fmaxf(d[1] + bb.y, 0.0f);
            float h2 = fmaxf(d[2] + bb.x, 0.0f);
            float h3 = fmaxf(d[3] + bb.y, 0.0f);
            int kt3 = nt >> 1, off = (nt & 1) * 2;
            split2(h0, h1, A3h[kt3][off],     A3l[kt3][off]);
            split2(h2, h3, A3h[kt3][off + 1], A3l[kt3][off + 1]);
        }

        // ---- layer3 (K=32, N=32) + bias, store ----
        #pragma unroll
        for (int nt = 0; nt < 4; ++nt) {
            float d[4] = {0.f, 0.f, 0.f, 0.f};
            #pragma unroll
            for (int kt = 0; kt < 2; ++kt) {
                uint4 B = g_W3f[(nt * 2 + kt) * 32 + lane];
                mma_bf16(d, A3h[kt], B.x, B.y);
                mma_bf16(d, A3h[kt], B.z, B.w);
                mma_bf16(d, A3l[kt], B.x, B.y);
            }
            float2 b3 = *reinterpret_cast<const float2*>(bd3 + 8 * nt + 2 * t);
            if (ra < nrows)
                *reinterpret_cast<float2*>(out + (size_t)ra * 32 + 8 * nt + 2 * t) = make_float2(d[0] + b3.x, d[1] + b3.y);
            if (rb < nrows)
                *reinterpret_cast<float2*>(out + (size_t)rb * 32 + 8 * nt + 2 * t) = make_float2(d[2] + b3.x, d[3] + b3.y);
        }
    }
}

extern "C" void kernel_launch(void* const* d_in, const int* in_sizes, int n_in,
                              void* d_out, int out_size)
{
    const float* t   = (const float*)d_in[0];
    const float* emb = (const float*)d_in[1];
    const float* pa  = (const float*)d_in[3];
    const float* Wt1 = (const float*)d_in[9];
    const float* bt1 = (const float*)d_in[10];
    const float* Wt2 = (const float*)d_in[11];
    const float* bt2 = (const float*)d_in[12];
    const float* Wd1 = (const float*)d_in[13];
    const float* bd1 = (const float*)d_in[14];
    const float* Wd2 = (const float*)d_in[15];
    const float* bd2 = (const float*)d_in[16];
    const float* Wd3 = (const float*)d_in[17];
    const float* bd3 = (const float*)d_in[18];
    float* out = (float*)d_out;

    const int nrows = in_sizes[1] / HID;

    prep_kernel<<<1, 256>>>(t, pa, Wt1, bt1, Wt2, bt2, Wd1, bd1, Wd2, Wd3);
    velo_kernel<<<(nrows + 127) / 128, TPB>>>(emb, bd2, bd3, out, nrows);
}

// round 10
// speedup vs baseline: 3.2150x; 1.0217x over previous
#include <cuda_runtime.h>
#include <cuda_bf16.h>
#include <cstdint>

// velocity = MLP(concat(zone_embedding, person_attrs, time_vec)).
// GCN layers are dead code w.r.t. the output; person/time layer-1
// contributions are row-constant, folded into g_c1 by the prep kernel.
//
// R10 = R9 (bf16 3-term-split mma.m16n8k16, register-chained layers) with
// loop interchange: nt-outer / m-tile-inner. Each weight B-fragment is
// loaded ONCE and feeds two independent accumulation chains (both m-tiles),
// halving B LDGs and doubling MMA ILP — targeting the latency bound that
// R9's flat profile (tensor 28%, issue 22%, nothing saturated) showed.

#define HID 32
#define H1  64
#define TPB 128            // 4 warps, 32 rows/warp, 128 rows/block

typedef uint32_t u32;

__device__ __align__(16) float g_c1[H1];     // folded layer-1 bias
__device__ uint4 g_W1f[16 * 32];             // (nt8*2 + kt2) x lane
__device__ uint4 g_W2f[16 * 32];             // (nt4*4 + kt4) x lane
__device__ uint4 g_W3f[ 8 * 32];             // (nt4*2 + kt2) x lane

// pack pair (x0 -> low half, x1 -> high half) into bf16x2 hi, residual lo.
__device__ __forceinline__ void split2(float x0, float x1, u32& hi, u32& lo) {
    asm("cvt.rn.bf16x2.f32 %0, %1, %2;" : "=r"(hi) : "f"(x1), "f"(x0));
    float h0 = __uint_as_float(hi << 16);
    float h1 = __uint_as_float(hi & 0xffff0000u);
    float r0 = x0 - h0;
    float r1 = x1 - h1;
    asm("cvt.rn.bf16x2.f32 %0, %1, %2;" : "=r"(lo) : "f"(r1), "f"(r0));
}

__device__ __forceinline__ void mma_bf16(float d[4], const u32 a[4], u32 b0, u32 b1) {
    asm("mma.sync.aligned.m16n8k16.row.col.f32.bf16.bf16.f32 "
        "{%0,%1,%2,%3}, {%4,%5,%6,%7}, {%8,%9}, {%0,%1,%2,%3};"
        : "+f"(d[0]), "+f"(d[1]), "+f"(d[2]), "+f"(d[3])
        : "r"(a[0]), "r"(a[1]), "r"(a[2]), "r"(a[3]), "r"(b0), "r"(b1));
}

// ---------------------------------------------------------------------------
// Prep: fold c1, pack all weight B-fragments (hi/lo). One block, 256 threads.
// ---------------------------------------------------------------------------
__global__ void prep_kernel(const float* __restrict__ t,
                            const float* __restrict__ pa,
                            const float* __restrict__ Wt1, const float* __restrict__ bt1,
                            const float* __restrict__ Wt2, const float* __restrict__ bt2,
                            const float* __restrict__ Wd1, const float* __restrict__ bd1,
                            const float* __restrict__ Wd2, const float* __restrict__ Wd3)
{
    __shared__ float u[16];
    __shared__ float tv[16];
    const int tid = threadIdx.x;

    if (tid < 16) u[tid] = fmaxf(fmaf(t[0], Wt1[tid], bt1[tid]), 0.0f);
    __syncthreads();
    if (tid < 16) {
        float a = bt2[tid];
        #pragma unroll
        for (int i = 0; i < 16; i++) a = fmaf(u[i], Wt2[i * 16 + tid], a);
        tv[tid] = a;
    }
    __syncthreads();
    if (tid < H1) {
        float a = bd1[tid];
        #pragma unroll
        for (int p = 0; p < 8; p++)  a = fmaf(pa[p], Wd1[(HID + p) * H1 + tid], a);
        #pragma unroll
        for (int i = 0; i < 16; i++) a = fmaf(tv[i], Wd1[(HID + 8 + i) * H1 + tid], a);
        g_c1[tid] = a;
    }

    for (int idx = tid; idx < 1280; idx += 256) {
        const float* W;
        int stride, nt, kt, lane;
        uint4* dst;
        int slot;
        if (idx < 512) {                 // W1: zone part of Wd1 [32 x 64]
            int s = idx;        lane = s & 31; int ntkt = s >> 5;
            nt = ntkt >> 1; kt = ntkt & 1;
            W = Wd1; stride = 64; dst = g_W1f; slot = s;
        } else if (idx < 1024) {         // W2 [64 x 32]
            int s = idx - 512;  lane = s & 31; int ntkt = s >> 5;
            nt = ntkt >> 2; kt = ntkt & 3;
            W = Wd2; stride = 32; dst = g_W2f; slot = s;
        } else {                         // W3 [32 x 32]
            int s = idx - 1024; lane = s & 31; int ntkt = s >> 5;
            nt = ntkt >> 1; kt = ntkt & 1;
            W = Wd3; stride = 32; dst = g_W3f; slot = s;
        }
        int g = lane >> 2, tt = lane & 3;
        int col  = 8 * nt + g;
        int krow = 16 * kt + 2 * tt;
        float w00 = W[(krow    ) * stride + col];
        float w01 = W[(krow + 1) * stride + col];
        float w10 = W[(krow + 8) * stride + col];
        float w11 = W[(krow + 9) * stride + col];
        uint4 f;
        split2(w00, w01, f.x, f.z);
        split2(w10, w11, f.y, f.w);
        dst[slot] = f;
    }
}

// ---------------------------------------------------------------------------
// Main: 4 warps/block, 32 rows/warp (2 m16 tiles, both live per layer).
// ---------------------------------------------------------------------------
__global__ void __launch_bounds__(TPB)
velo_kernel(const float* __restrict__ emb,
            const float* __restrict__ bd2, const float* __restrict__ bd3,
            float* __restrict__ out, int nrows)
{
    const int warp = threadIdx.x >> 5;
    const int lane = threadIdx.x & 31;
    const int g = lane >> 2, t = lane & 3;
    const int row_base = blockIdx.x * 128 + warp * 32;
    if (row_base >= nrows) return;

    const float2 zero2 = make_float2(0.0f, 0.0f);
    int ra[2], rb[2];
    #pragma unroll
    for (int mt = 0; mt < 2; ++mt) { ra[mt] = row_base + 16 * mt + g; rb[mt] = ra[mt] + 8; }

    // ---- A1 fragments for both m-tiles ----
    u32 A1h[2][2][4], A1l[2][2][4];
    #pragma unroll
    for (int mt = 0; mt < 2; ++mt) {
        #pragma unroll
        for (int kt = 0; kt < 2; ++kt) {
            float2 p0 = (ra[mt] < nrows) ? *reinterpret_cast<const float2*>(emb + (size_t)ra[mt] * 32 + 16 * kt + 2 * t)     : zero2;
            float2 p1 = (rb[mt] < nrows) ? *reinterpret_cast<const float2*>(emb + (size_t)rb[mt] * 32 + 16 * kt + 2 * t)     : zero2;
            float2 p2 = (ra[mt] < nrows) ? *reinterpret_cast<const float2*>(emb + (size_t)ra[mt] * 32 + 16 * kt + 8 + 2 * t) : zero2;
            float2 p3 = (rb[mt] < nrows) ? *reinterpret_cast<const float2*>(emb + (size_t)rb[mt] * 32 + 16 * kt + 8 + 2 * t) : zero2;
            split2(p0.x, p0.y, A1h[mt][kt][0], A1l[mt][kt][0]);
            split2(p1.x, p1.y, A1h[mt][kt][1], A1l[mt][kt][1]);
            split2(p2.x, p2.y, A1h[mt][kt][2], A1l[mt][kt][2]);
            split2(p3.x, p3.y, A1h[mt][kt][3], A1l[mt][kt][3]);
        }
    }

    // ---- layer1 (K=32, N=64): nt-outer, both m-tiles per B fragment ----
    u32 A2h[2][4][4], A2l[2][4][4];
    #pragma unroll
    for (int nt = 0; nt < 8; ++nt) {
        float d[2][4] = {{0.f,0.f,0.f,0.f},{0.f,0.f,0.f,0.f}};
        #pragma unroll
        for (int kt = 0; kt < 2; ++kt) {
            uint4 B = g_W1f[(nt * 2 + kt) * 32 + lane];
            #pragma unroll
            for (int mt = 0; mt < 2; ++mt) {
                mma_bf16(d[mt], A1h[mt][kt], B.x, B.y);
                mma_bf16(d[mt], A1h[mt][kt], B.z, B.w);
                mma_bf16(d[mt], A1l[mt][kt], B.x, B.y);
            }
        }
        float2 cb = *reinterpret_cast<const float2*>(g_c1 + 8 * nt + 2 * t);
        int kt2 = nt >> 1, off = (nt & 1) * 2;
        #pragma unroll
        for (int mt = 0; mt < 2; ++mt) {
            float h0 = fmaxf(d[mt][0] + cb.x, 0.0f);
            float h1 = fmaxf(d[mt][1] + cb.y, 0.0f);
            float h2 = fmaxf(d[mt][2] + cb.x, 0.0f);
            float h3 = fmaxf(d[mt][3] + cb.y, 0.0f);
            split2(h0, h1, A2h[mt][kt2][off],     A2l[mt][kt2][off]);
            split2(h2, h3, A2h[mt][kt2][off + 1], A2l[mt][kt2][off + 1]);
        }
    }

    // ---- layer2 (K=64, N=32) ----
    u32 A3h[2][2][4], A3l[2][2][4];
    #pragma unroll
    for (int nt = 0; nt < 4; ++nt) {
        float d[2][4] = {{0.f,0.f,0.f,0.f},{0.f,0.f,0.f,0.f}};
        #pragma unroll
        for (int kt = 0; kt < 4; ++kt) {
            uint4 B = g_W2f[(nt * 4 + kt) * 32 + lane];
            #pragma unroll
            for (int mt = 0; mt < 2; ++mt) {
                mma_bf16(d[mt], A2h[mt][kt], B.x, B.y);
                mma_bf16(d[mt], A2h[mt][kt], B.z, B.w);
                mma_bf16(d[mt], A2l[mt][kt], B.x, B.y);
            }
        }
        float2 bb = *reinterpret_cast<const float2*>(bd2 + 8 * nt + 2 * t);
        int kt3 = nt >> 1, off = (nt & 1) * 2;
        #pragma unroll
        for (int mt = 0; mt < 2; ++mt) {
            float h0 = fmaxf(d[mt][0] + bb.x, 0.0f);
            float h1 = fmaxf(d[mt][1] + bb.y, 0.0f);
            float h2 = fmaxf(d[mt][2] + bb.x, 0.0f);
            float h3 = fmaxf(d[mt][3] + bb.y, 0.0f);
            split2(h0, h1, A3h[mt][kt3][off],     A3l[mt][kt3][off]);
            split2(h2, h3, A3h[mt][kt3][off + 1], A3l[mt][kt3][off + 1]);
        }
    }

    // ---- layer3 (K=32, N=32) + bias, store ----
    #pragma unroll
    for (int nt = 0; nt < 4; ++nt) {
        float d[2][4] = {{0.f,0.f,0.f,0.f},{0.f,0.f,0.f,0.f}};
        #pragma unroll
        for (int kt = 0; kt < 2; ++kt) {
            uint4 B = g_W3f[(nt * 2 + kt) * 32 + lane];
            #pragma unroll
            for (int mt = 0; mt < 2; ++mt) {
                mma_bf16(d[mt], A3h[mt][kt], B.x, B.y);
                mma_bf16(d[mt], A3h[mt][kt], B.z, B.w);
                mma_bf16(d[mt], A3l[mt][kt], B.x, B.y);
            }
        }
        float2 b3 = *reinterpret_cast<const float2*>(bd3 + 8 * nt + 2 * t);
        #pragma unroll
        for (int mt = 0; mt < 2; ++mt) {
            if (ra[mt] < nrows)
                *reinterpret_cast<float2*>(out + (size_t)ra[mt] * 32 + 8 * nt + 2 * t) = make_float2(d[mt][0] + b3.x, d[mt][1] + b3.y);
            if (rb[mt] < nrows)
                *reinterpret_cast<float2*>(out + (size_t)rb[mt] * 32 + 8 * nt + 2 * t) = make_float2(d[mt][2] + b3.x, d[mt][3] + b3.y);
        }
    }
}

extern "C" void kernel_launch(void* const* d_in, const int* in_sizes, int n_in,
                              void* d_out, int out_size)
{
    const float* t   = (const float*)d_in[0];
    const float* emb = (const float*)d_in[1];
    const float* pa  = (const float*)d_in[3];
    const float* Wt1 = (const float*)d_in[9];
    const float* bt1 = (const float*)d_in[10];
    const float* Wt2 = (const float*)d_in[11];
    const float* bt2 = (const float*)d_in[12];
    const float* Wd1 = (const float*)d_in[13];
    const float* bd1 = (const float*)d_in[14];
    const float* Wd2 = (const float*)d_in[15];
    const float* bd2 = (const float*)d_in[16];
    const float* Wd3 = (const float*)d_in[17];
    const float* bd3 = (const float*)d_in[18];
    float* out = (float*)d_out;

    const int nrows = in_sizes[1] / HID;

    prep_kernel<<<1, 256>>>(t, pa, Wt1, bt1, Wt2, bt2, Wd1, bd1, Wd2, Wd3);
    velo_kernel<<<(nrows + 127) / 128, TPB>>>(emb, bd2, bd3, out, nrows);
}

// round 11
// speedup vs baseline: 3.3374x; 1.0381x over previous
#include <cuda_runtime.h>
#include <cuda_bf16.h>
#include <cstdint>

// velocity = MLP(concat(zone_embedding, person_attrs, time_vec)).
// GCN layers are dead code w.r.t. the output; person/time layer-1
// contributions are row-constant, folded into c1 (now per-block).
//
// R11 = R10 (bf16 3-term-split mma.m16n8k16, register-chained layers,
// nt-outer/mt-inner ILP) with the prep kernel MERGED: each block folds c1
// and packs the 1280 weight B-fragments into static smem itself (20KB,
// 3 blocks/SM unchanged). Saves the ~2.6us prep-launch serialization seen
// as wall(19.2) - velo(16.6), and upgrades B-frag reads LDG->LDS.

#define HID 32
#define H1  64
#define TPB 128            // 4 warps, 32 rows/warp, 128 rows/block

typedef uint32_t u32;

// pack pair (x0 -> low half, x1 -> high half) into bf16x2 hi, residual lo.
__device__ __forceinline__ void split2(float x0, float x1, u32& hi, u32& lo) {
    asm("cvt.rn.bf16x2.f32 %0, %1, %2;" : "=r"(hi) : "f"(x1), "f"(x0));
    float h0 = __uint_as_float(hi << 16);
    float h1 = __uint_as_float(hi & 0xffff0000u);
    float r0 = x0 - h0;
    float r1 = x1 - h1;
    asm("cvt.rn.bf16x2.f32 %0, %1, %2;" : "=r"(lo) : "f"(r1), "f"(r0));
}

__device__ __forceinline__ void mma_bf16(float d[4], const u32 a[4], u32 b0, u32 b1) {
    asm("mma.sync.aligned.m16n8k16.row.col.f32.bf16.bf16.f32 "
        "{%0,%1,%2,%3}, {%4,%5,%6,%7}, {%8,%9}, {%0,%1,%2,%3};"
        : "+f"(d[0]), "+f"(d[1]), "+f"(d[2]), "+f"(d[3])
        : "r"(a[0]), "r"(a[1]), "r"(a[2]), "r"(a[3]), "r"(b0), "r"(b1));
}

// ---------------------------------------------------------------------------
// Single kernel: per-block c1 fold + B-fragment packing (smem), then the
// register-chained 3-layer MLP on 32 rows/warp (2 m16 tiles).
// s_frag: W1 [0,512), W2 [512,1024), W3 [1024,1280).
// ---------------------------------------------------------------------------
__global__ void __launch_bounds__(TPB)
velo_kernel(const float* __restrict__ emb,
            const float* __restrict__ t,   const float* __restrict__ pa,
            const float* __restrict__ Wt1, const float* __restrict__ bt1,
            const float* __restrict__ Wt2, const float* __restrict__ bt2,
            const float* __restrict__ Wd1, const float* __restrict__ bd1,
            const float* __restrict__ Wd2, const float* __restrict__ bd2,
            const float* __restrict__ Wd3, const float* __restrict__ bd3,
            float* __restrict__ out, int nrows)
{
    __shared__ __align__(16) uint4 s_frag[1280];
    __shared__ __align__(16) float s_c1[64];
    __shared__ float s_u[16], s_tv[16];

    const int tid = threadIdx.x;

    // ---- fold time/person into c1 (redundant per block; tiny) ----
    if (tid < 16) s_u[tid] = fmaxf(fmaf(t[0], Wt1[tid], bt1[tid]), 0.0f);
    __syncthreads();
    if (tid < 16) {
        float a = bt2[tid];
        #pragma unroll
        for (int i = 0; i < 16; i++) a = fmaf(s_u[i], Wt2[i * 16 + tid], a);
        s_tv[tid] = a;
    }
    __syncthreads();
    if (tid < H1) {
        float a = bd1[tid];
        #pragma unroll
        for (int p = 0; p < 8; p++)  a = fmaf(pa[p], Wd1[(HID + p) * H1 + tid], a);
        #pragma unroll
        for (int i = 0; i < 16; i++) a = fmaf(s_tv[i], Wd1[(HID + 8 + i) * H1 + tid], a);
        s_c1[tid] = a;
    }

    // ---- pack all weight B-fragments into smem ----
    #pragma unroll
    for (int idx = tid; idx < 1280; idx += TPB) {
        const float* W;
        int stride, nt, kt, lane, slot;
        if (idx < 512) {                 // W1: zone part of Wd1 [32 x 64]
            int s = idx;        lane = s & 31; int ntkt = s >> 5;
            nt = ntkt >> 1; kt = ntkt & 1;
            W = Wd1; stride = 64; slot = s;
        } else if (idx < 1024) {         // W2 [64 x 32]
            int s = idx - 512;  lane = s & 31; int ntkt = s >> 5;
            nt = ntkt >> 2; kt = ntkt & 3;
            W = Wd2; stride = 32; slot = 512 + s;
        } else {                         // W3 [32 x 32]
            int s = idx - 1024; lane = s & 31; int ntkt = s >> 5;
            nt = ntkt >> 1; kt = ntkt & 1;
            W = Wd3; stride = 32; slot = 1024 + s;
        }
        int gg = lane >> 2, tt = lane & 3;
        int col  = 8 * nt + gg;
        int krow = 16 * kt + 2 * tt;
        float w00 = W[(krow    ) * stride + col];
        float w01 = W[(krow + 1) * stride + col];
        float w10 = W[(krow + 8) * stride + col];
        float w11 = W[(krow + 9) * stride + col];
        uint4 f;
        split2(w00, w01, f.x, f.z);
        split2(w10, w11, f.y, f.w);
        s_frag[slot] = f;
    }
    __syncthreads();

    const int warp = tid >> 5;
    const int lane = tid & 31;
    const int g = lane >> 2, tq = lane & 3;
    const int row_base = blockIdx.x * 128 + warp * 32;
    if (row_base >= nrows) return;      // safe: after the only barrier

    const float2 zero2 = make_float2(0.0f, 0.0f);
    int ra[2], rb[2];
    #pragma unroll
    for (int mt = 0; mt < 2; ++mt) { ra[mt] = row_base + 16 * mt + g; rb[mt] = ra[mt] + 8; }

    // ---- A1 fragments for both m-tiles ----
    u32 A1h[2][2][4], A1l[2][2][4];
    #pragma unroll
    for (int mt = 0; mt < 2; ++mt) {
        #pragma unroll
        for (int kt = 0; kt < 2; ++kt) {
            float2 p0 = (ra[mt] < nrows) ? *reinterpret_cast<const float2*>(emb + (size_t)ra[mt] * 32 + 16 * kt + 2 * tq)     : zero2;
            float2 p1 = (rb[mt] < nrows) ? *reinterpret_cast<const float2*>(emb + (size_t)rb[mt] * 32 + 16 * kt + 2 * tq)     : zero2;
            float2 p2 = (ra[mt] < nrows) ? *reinterpret_cast<const float2*>(emb + (size_t)ra[mt] * 32 + 16 * kt + 8 + 2 * tq) : zero2;
            float2 p3 = (rb[mt] < nrows) ? *reinterpret_cast<const float2*>(emb + (size_t)rb[mt] * 32 + 16 * kt + 8 + 2 * tq) : zero2;
            split2(p0.x, p0.y, A1h[mt][kt][0], A1l[mt][kt][0]);
            split2(p1.x, p1.y, A1h[mt][kt][1], A1l[mt][kt][1]);
            split2(p2.x, p2.y, A1h[mt][kt][2], A1l[mt][kt][2]);
            split2(p3.x, p3.y, A1h[mt][kt][3], A1l[mt][kt][3]);
        }
    }

    // ---- layer1 (K=32, N=64): nt-outer, both m-tiles per B fragment ----
    u32 A2h[2][4][4], A2l[2][4][4];
    #pragma unroll
    for (int nt = 0; nt < 8; ++nt) {
        float d[2][4] = {{0.f,0.f,0.f,0.f},{0.f,0.f,0.f,0.f}};
        #pragma unroll
        for (int kt = 0; kt < 2; ++kt) {
            uint4 B = s_frag[(nt * 2 + kt) * 32 + lane];
            #pragma unroll
            for (int mt = 0; mt < 2; ++mt) {
                mma_bf16(d[mt], A1h[mt][kt], B.x, B.y);
                mma_bf16(d[mt], A1h[mt][kt], B.z, B.w);
                mma_bf16(d[mt], A1l[mt][kt], B.x, B.y);
            }
        }
        float2 cb = *reinterpret_cast<const float2*>(s_c1 + 8 * nt + 2 * tq);
        int kt2 = nt >> 1, off = (nt & 1) * 2;
        #pragma unroll
        for (int mt = 0; mt < 2; ++mt) {
            float h0 = fmaxf(d[mt][0] + cb.x, 0.0f);
            float h1 = fmaxf(d[mt][1] + cb.y, 0.0f);
            float h2 = fmaxf(d[mt][2] + cb.x, 0.0f);
            float h3 = fmaxf(d[mt][3] + cb.y, 0.0f);
            split2(h0, h1, A2h[mt][kt2][off],     A2l[mt][kt2][off]);
            split2(h2, h3, A2h[mt][kt2][off + 1], A2l[mt][kt2][off + 1]);
        }
    }

    // ---- layer2 (K=64, N=32) ----
    u32 A3h[2][2][4], A3l[2][2][4];
    #pragma unroll
    for (int nt = 0; nt < 4; ++nt) {
        float d[2][4] = {{0.f,0.f,0.f,0.f},{0.f,0.f,0.f,0.f}};
        #pragma unroll
        for (int kt = 0; kt < 4; ++kt) {
            uint4 B = s_frag[512 + (nt * 4 + kt) * 32 + lane];
            #pragma unroll
            for (int mt = 0; mt < 2; ++mt) {
                mma_bf16(d[mt], A2h[mt][kt], B.x, B.y);
                mma_bf16(d[mt], A2h[mt][kt], B.z, B.w);
                mma_bf16(d[mt], A2l[mt][kt], B.x, B.y);
            }
        }
        float2 bb = *reinterpret_cast<const float2*>(bd2 + 8 * nt + 2 * tq);
        int kt3 = nt >> 1, off = (nt & 1) * 2;
        #pragma unroll
        for (int mt = 0; mt < 2; ++mt) {
            float h0 = fmaxf(d[mt][0] + bb.x, 0.0f);
            float h1 = fmaxf(d[mt][1] + bb.y, 0.0f);
            float h2 = fmaxf(d[mt][2] + bb.x, 0.0f);
            float h3 = fmaxf(d[mt][3] + bb.y, 0.0f);
            split2(h0, h1, A3h[mt][kt3][off],     A3l[mt][kt3][off]);
            split2(h2, h3, A3h[mt][kt3][off + 1], A3l[mt][kt3][off + 1]);
        }
    }

    // ---- layer3 (K=32, N=32) + bias, store ----
    #pragma unroll
    for (int nt = 0; nt < 4; ++nt) {
        float d[2][4] = {{0.f,0.f,0.f,0.f},{0.f,0.f,0.f,0.f}};
        #pragma unroll
        for (int kt = 0; kt < 2; ++kt) {
            uint4 B = s_frag[1024 + (nt * 2 + kt) * 32 + lane];
            #pragma unroll
            for (int mt = 0; mt < 2; ++mt) {
                mma_bf16(d[mt], A3h[mt][kt], B.x, B.y);
                mma_bf16(d[mt], A3h[mt][kt], B.z, B.w);
                mma_bf16(d[mt], A3l[mt][kt], B.x, B.y);
            }
        }
        float2 b3 = *reinterpret_cast<const float2*>(bd3 + 8 * nt + 2 * tq);
        #pragma unroll
        for (int mt = 0; mt < 2; ++mt) {
            if (ra[mt] < nrows)
                *reinterpret_cast<float2*>(out + (size_t)ra[mt] * 32 + 8 * nt + 2 * tq) = make_float2(d[mt][0] + b3.x, d[mt][1] + b3.y);
            if (rb[mt] < nrows)
                *reinterpret_cast<float2*>(out + (size_t)rb[mt] * 32 + 8 * nt + 2 * tq) = make_float2(d[mt][2] + b3.x, d[mt][3] + b3.y);
        }
    }
}

extern "C" void kernel_launch(void* const* d_in, const int* in_sizes, int n_in,
                              void* d_out, int out_size)
{
    const float* t   = (const float*)d_in[0];
    const float* emb = (const float*)d_in[1];
    const float* pa  = (const float*)d_in[3];
    const float* Wt1 = (const float*)d_in[9];
    const float* bt1 = (const float*)d_in[10];
    const float* Wt2 = (const float*)d_in[11];
    const float* bt2 = (const float*)d_in[12];
    const float* Wd1 = (const float*)d_in[13];
    const float* bd1 = (const float*)d_in[14];
    const float* Wd2 = (const float*)d_in[15];
    const float* bd2 = (const float*)d_in[16];
    const float* Wd3 = (const float*)d_in[17];
    const float* bd3 = (const float*)d_in[18];
    float* out = (float*)d_out;

    const int nrows = in_sizes[1] / HID;

    velo_kernel<<<(nrows + 127) / 128, TPB>>>(emb, t, pa, Wt1, bt1, Wt2, bt2,
                                              Wd1, bd1, Wd2, bd2, Wd3, bd3,
                                              out, nrows);
}